// round 13
// baseline (speedup 1.0000x reference)
#include <cuda_runtime.h>
#include <cuda_fp16.h>
#include <cstdint>
#include <cstddef>

#define B_SZ 1024
#define NF   800
#define L1D  1024
#define NT_IT 50          // 50 k-iterations of 16
#define K2T   32          // iterations with 2-term B (k < 512); rest single-term

// Scratch (no allocation allowed — __device__ globals)
__device__ __half g_a[B_SZ * NF];      // vals fp16 (RN), (B,800) row-major
__device__ __half g_bh[L1D * NF];      // ft_w^T hi, (n,k) k-contig
__device__ __half g_bl[L1D * NF];      // ft_w^T lo
__device__ float  g_pa[B_SZ * L1D];    // raw features (no bias/clip)

// ---------------------------------------------------------------------------
// Kernel 0: transpose ft_w (800x1024 -> 1024x800) and split into fp16 hi/lo.
// ---------------------------------------------------------------------------
__global__ __launch_bounds__(256) void prep_bt_kernel(const float* __restrict__ w) {
    __shared__ float ts[32][33];
    int tx = threadIdx.x & 31, ty = threadIdx.x >> 5;   // 32 x 8
    int kbase = blockIdx.y * 32, nbase = blockIdx.x * 32;
#pragma unroll
    for (int i = 0; i < 4; i++)
        ts[ty + i * 8][tx] = w[(size_t)(kbase + ty + i * 8) * L1D + nbase + tx];
    __syncthreads();
#pragma unroll
    for (int i = 0; i < 4; i++) {
        int n = nbase + ty + i * 8;
        int k = kbase + tx;
        float v = ts[tx][ty + i * 8];
        __half h = __float2half_rn(v);
        g_bh[(size_t)n * NF + k] = h;
        g_bl[(size_t)n * NF + k] = __float2half_rn(v - __half2float(h));
    }
}

// ---------------------------------------------------------------------------
// Kernel 1: conv(3x3,s10,p1) + clip + sigmoid gate -> fp16 vals. 256 threads.
// ---------------------------------------------------------------------------
__global__ __launch_bounds__(256) void conv_act_kernel(
    const float* __restrict__ images, const float* __restrict__ conv_w) {
    __shared__ float w[216];
    __shared__ float s[30][3][98];
    int t = threadIdx.x;
    int b = blockIdx.x;
    for (int i = t; i < 216; i += 256) w[i] = conv_w[i];
    for (int i = t; i < 3 * 98; i += 256) s[0][i / 98][i % 98] = 0.f;
    for (int i = t; i < 30 * 3; i += 256) s[i / 3][i % 3][0] = 0.f;
    __syncthreads();

    const float* img = images + (size_t)b * 3 * 96 * 96;
    for (int i = t; i < 29 * 3 * 96; i += 256) {
        int rr = i / 288 + 1; int rem = i - (rr - 1) * 288;
        int c = rem / 96;  int x = rem - c * 96;
        int iy = (rr / 3) * 10 - 1 + rr % 3;
        s[rr][c][x + 1] = __ldg(img + c * 9216 + iy * 96 + x);
    }
    __syncthreads();

    if (t < 100) {
        int oy = t / 10, ox = t - oy * 10;
        float acc[8];
#pragma unroll
        for (int c8 = 0; c8 < 8; c8++) acc[c8] = 0.f;
#pragma unroll
        for (int ky = 0; ky < 3; ky++) {
            const float (*srow)[98] = s[3 * oy + ky];
#pragma unroll
            for (int ic = 0; ic < 3; ic++) {
#pragma unroll
                for (int kx = 0; kx < 3; kx++) {
                    float v = srow[ic][10 * ox + kx];
#pragma unroll
                    for (int c8 = 0; c8 < 8; c8++)
                        acc[c8] = fmaf(v, w[c8 * 27 + ic * 9 + ky * 3 + kx], acc[c8]);
                }
            }
        }
#pragma unroll
        for (int c8 = 0; c8 < 8; c8++) {
            float x  = fminf(fmaxf(acc[c8], -1.f), 1.f);
            float sg = 1.f / (1.f + __expf(-10.f * x));
            float vv = (sg > 0.5f) ? sg : 0.f;
            g_a[(size_t)b * NF + c8 * 100 + t] = __float2half_rn(vv);
        }
    }
}

// ---------------------------------------------------------------------------
// Kernel 2: GEMM, R5's best-measured config (8.7 cyc/mma): BM=64 BN=128,
// 256 thr, 8 warps (2x4), warp tile 32x32, scalar LDS frags, 2-stage cp.async.
// Terms: k<512 -> A*Bh + A*Bl; k>=512 -> A*Bh only. Raw partials -> g_pa.
// ---------------------------------------------------------------------------
__device__ __forceinline__ void mma_f16(float* d, const uint32_t* a, const uint32_t* b) {
    asm volatile(
        "mma.sync.aligned.m16n8k16.row.col.f32.f16.f16.f32 "
        "{%0,%1,%2,%3}, {%4,%5,%6,%7}, {%8,%9}, {%0,%1,%2,%3};\n"
        : "+f"(d[0]), "+f"(d[1]), "+f"(d[2]), "+f"(d[3])
        : "r"(a[0]), "r"(a[1]), "r"(a[2]), "r"(a[3]), "r"(b[0]), "r"(b[1]));
}
#define CP16(dst, src) \
    asm volatile("cp.async.ca.shared.global [%0], [%1], 16;\n" :: "r"(dst), "l"(src))

__global__ __launch_bounds__(256) void feat_mma_kernel() {
    __shared__ uint32_t As[2][64][12];
    __shared__ uint32_t Bh[2][128][12];
    __shared__ uint32_t Bl[2][128][12];

    const int t = threadIdx.x, lane = t & 31, wid = t >> 5;
    const int wm = wid >> 2, wn = wid & 3;           // 2 x 4 warps, 32x32 tiles
    const int bm = blockIdx.y * 64, bn = blockIdx.x * 128;

    float acc[2][4][4];
#pragma unroll
    for (int f = 0; f < 2; f++)
#pragma unroll
        for (int j = 0; j < 4; j++)
#pragma unroll
            for (int e = 0; e < 4; e++) acc[f][j][e] = 0.f;

    // staging: A (t<128: 1 chunk), Bh (all: 1 chunk), Bl (t>=128: 2 chunks)
    const int arow = t >> 1, aseg = t & 1;                 // t < 128
    const int bhrow = t >> 1, bhseg = t & 1;               // all threads
    const int blrow = t - 128;                             // t >= 128
    const __half* a_src  = g_a  + (size_t)(bm + arow) * NF + aseg * 8;
    const __half* bh_src = g_bh + (size_t)(bn + bhrow) * NF + bhseg * 8;
    const __half* bl_src = g_bl + (size_t)(bn + blrow) * NF;
    uint32_t a_dst[2], bh_dst[2], bl_dst0[2], bl_dst1[2];
#pragma unroll
    for (int s2 = 0; s2 < 2; s2++) {
        a_dst[s2]   = (uint32_t)__cvta_generic_to_shared(&As[s2][arow][aseg * 4]);
        bh_dst[s2]  = (uint32_t)__cvta_generic_to_shared(&Bh[s2][bhrow][bhseg * 4]);
        bl_dst0[s2] = (uint32_t)__cvta_generic_to_shared(&Bl[s2][blrow & 127][0]);
        bl_dst1[s2] = (uint32_t)__cvta_generic_to_shared(&Bl[s2][blrow & 127][4]);
    }

#define LOAD_STAGE(s2, k0, withBl)                               \
    do {                                                         \
        if (t < 128) CP16(a_dst[s2], a_src + (k0));              \
        CP16(bh_dst[s2], bh_src + (k0));                         \
        if ((withBl) && t >= 128) {                              \
            CP16(bl_dst0[s2], bl_src + (k0));                    \
            CP16(bl_dst1[s2], bl_src + (k0) + 8);                \
        }                                                        \
        asm volatile("cp.async.commit_group;\n");                \
    } while (0)

    LOAD_STAGE(0, 0, 1);

    const int r0 = wm * 32 + (lane >> 2);
    const int nb = wn * 32 + (lane >> 2);
    const int j0 = lane & 3;

    for (int it = 0; it < NT_IT; it++) {
        int buf = it & 1;
        if (it < NT_IT - 1) {
            LOAD_STAGE(buf ^ 1, (it + 1) * 16, (it + 1) < K2T);
            asm volatile("cp.async.wait_group 1;\n");
        } else {
            asm volatile("cp.async.wait_group 0;\n");
        }
        __syncthreads();

        uint32_t af[2][4];
#pragma unroll
        for (int f = 0; f < 2; f++) {
            int r = r0 + f * 16;
            af[f][0] = As[buf][r][j0];      af[f][1] = As[buf][r + 8][j0];
            af[f][2] = As[buf][r][j0 + 4];  af[f][3] = As[buf][r + 8][j0 + 4];
        }
        uint32_t bhf[4][2];
#pragma unroll
        for (int j = 0; j < 4; j++) {
            int r = nb + j * 8;
            bhf[j][0] = Bh[buf][r][j0]; bhf[j][1] = Bh[buf][r][j0 + 4];
        }
#pragma unroll
        for (int f = 0; f < 2; f++)
#pragma unroll
            for (int j = 0; j < 4; j++)
                mma_f16(acc[f][j], af[f], bhf[j]);

        if (it < K2T) {
            uint32_t blf[4][2];
#pragma unroll
            for (int j = 0; j < 4; j++) {
                int r = nb + j * 8;
                blf[j][0] = Bl[buf][r][j0]; blf[j][1] = Bl[buf][r][j0 + 4];
            }
#pragma unroll
            for (int f = 0; f < 2; f++)
#pragma unroll
                for (int j = 0; j < 4; j++)
                    mma_f16(acc[f][j], af[f], blf[j]);
        }
        __syncthreads();
    }

    // epilogue: raw partial -> g_pa
    const int q = lane & 3, g = lane >> 2;
#pragma unroll
    for (int f = 0; f < 2; f++) {
        int row0 = bm + wm * 32 + f * 16 + g;
#pragma unroll
        for (int j = 0; j < 4; j++) {
            int col = bn + wn * 32 + j * 8 + 2 * q;
            float2 o0 = {acc[f][j][0], acc[f][j][1]};
            float2 o1 = {acc[f][j][2], acc[f][j][3]};
            *(float2*)(g_pa + (size_t)row0 * L1D + col) = o0;
            *(float2*)(g_pa + (size_t)(row0 + 8) * L1D + col) = o1;
        }
    }
}

// ---------------------------------------------------------------------------
// Kernel 3: tail MLP, float4 everywhere. 2 samples per 512-thr CTA (512 CTAs),
// 8 warps per sample; lane L of warp q owns l0c block jc = q*128 + L*4 + {0..3}
// (for q>=4 this equals 512 + (q-4)*128 + L*4). w1 col = q*128 + L*4 always.
// l0[j] = clip(g_pa[j] + ft_b[j], 0, 1), fused.
// ---------------------------------------------------------------------------
__global__ __launch_bounds__(512) void tail_kernel(
    const float* __restrict__ ftb,
    const float* __restrict__ w1, const float* __restrict__ b1,
    const float* __restrict__ w2, const float* __restrict__ b2,
    const float* __restrict__ w3, const float* __restrict__ b3,
    float* __restrict__ out) {
    __shared__ float part[2][8][15];
    __shared__ float h1s[2][15];

    const int t = threadIdx.x, lane = t & 31, wid = t >> 5;
    const int sl = wid >> 3, q = wid & 7;        // sample-local, eighth
    const int sample = blockIdx.x * 2 + sl;
    const float* pa = g_pa + (size_t)sample * L1D;
    const float KCst = 127.f / 128.f;

    const int jb = q * 128 + lane * 4;           // base index (also w1 column)
    float c[4];
    {
        float4 p0 = *(const float4*)(pa + (q < 4 ? jb : jb - 512));
        float4 f0 = __ldg((const float4*)(ftb + (q < 4 ? jb : jb - 512)));
        float s0x = fminf(fmaxf(p0.x + f0.x, 0.f), 1.f);
        float s0y = fminf(fmaxf(p0.y + f0.y, 0.f), 1.f);
        float s0z = fminf(fmaxf(p0.z + f0.z, 0.f), 1.f);
        float s0w = fminf(fmaxf(p0.w + f0.w, 0.f), 1.f);
        if (q < 4) {
            float4 p1 = *(const float4*)(pa + jb + 512);
            float4 f1 = __ldg((const float4*)(ftb + jb + 512));
            c[0] = s0x * fminf(fmaxf(p1.x + f1.x, 0.f), 1.f) * KCst;
            c[1] = s0y * fminf(fmaxf(p1.y + f1.y, 0.f), 1.f) * KCst;
            c[2] = s0z * fminf(fmaxf(p1.z + f1.z, 0.f), 1.f) * KCst;
            c[3] = s0w * fminf(fmaxf(p1.w + f1.w, 0.f), 1.f) * KCst;
        } else {
            c[0] = s0x * KCst; c[1] = s0y * KCst;
            c[2] = s0z * KCst; c[3] = s0w * KCst;
        }
    }

    float a[15];
#pragma unroll
    for (int o = 0; o < 15; o++) a[o] = 0.f;
#pragma unroll
    for (int o = 0; o < 15; o++) {
        float4 wv = __ldg((const float4*)(w1 + (size_t)o * L1D + jb));
        a[o] = fmaf(c[0], wv.x, fmaf(c[1], wv.y, fmaf(c[2], wv.z, c[3] * wv.w)));
    }
#pragma unroll
    for (int s = 16; s; s >>= 1)
#pragma unroll
        for (int o = 0; o < 15; o++)
            a[o] += __shfl_xor_sync(0xffffffffu, a[o], s);
    if (lane < 15) part[sl][q][lane] = a[lane];
    __syncthreads();

    if (q == 0) {
        if (lane < 15) {
            float h = __ldg(b1 + lane);
#pragma unroll
            for (int p = 0; p < 8; p++) h += part[sl][p][lane];
            h1s[sl][lane] = fmaxf(h, 0.f);
        }
        __syncwarp();
        float h2 = __ldg(b2 + lane);
#pragma unroll
        for (int k = 0; k < 15; k++)
            h2 = fmaf(h1s[sl][k], __ldg(w2 + lane * 15 + k), h2);
        h2 = fmaxf(h2, 0.f);
        float ov = h2 * __ldg(w3 + lane);
#pragma unroll
        for (int s = 16; s; s >>= 1) ov += __shfl_xor_sync(0xffffffffu, ov, s);
        if (lane == 0) out[sample] = ov + __ldg(b3);
    }
}

// ---------------------------------------------------------------------------
extern "C" void kernel_launch(void* const* d_in, const int* in_sizes, int n_in,
                              void* d_out, int out_size) {
    const float *images = 0, *conv_w = 0, *ft_w = 0, *ft_b = 0;
    const float *w1 = 0, *b1 = 0, *w2 = 0, *b2 = 0, *w3 = 0, *b3 = 0;

    for (int i = 0; i < n_in; i++) {
        const float* p = (const float*)d_in[i];
        switch (in_sizes[i]) {
            case 28311552: images = p; break;
            case 216:      conv_w = p; break;
            case 819200:   ft_w   = p; break;
            case 1024:     ft_b   = p; break;
            case 15360:    w1     = p; break;
            case 15:       b1     = p; break;
            case 480:      w2     = p; break;
            case 32:       if (!b2) b2 = p; else w3 = p; break;
            case 1:        b3     = p; break;
            default: break;
        }
    }
    float* out = (float*)d_out;

    dim3 gt(L1D / 32, NF / 32);      // 32 x 25
    prep_bt_kernel<<<gt, 256>>>(ft_w);
    conv_act_kernel<<<B_SZ, 256>>>(images, conv_w);

    dim3 g2(L1D / 128, B_SZ / 64);   // 8 x 16 = 128 CTAs
    feat_mma_kernel<<<g2, 256>>>();

    tail_kernel<<<B_SZ / 2, 512>>>(ft_b, w1, b1, w2, b2, w3, b3, out);
}

// round 14
// speedup vs baseline: 1.0307x; 1.0307x over previous
#include <cuda_runtime.h>
#include <cuda_fp16.h>
#include <cstdint>
#include <cstddef>

#define B_SZ 1024
#define NF   800
#define L1D  1024
#define NT_IT 50          // k-iterations of 16
#define K2T   32          // iterations with 2-term B (k < 512); rest 1-term

// Scratch (no allocation allowed — __device__ globals)
__device__ __half g_a[B_SZ * NF];      // vals fp16 (RN), (B,800) row-major
__device__ __half g_bh[L1D * NF];      // ft_w^T hi, (n,k) k-contig
__device__ __half g_bl[L1D * NF];      // ft_w^T lo
__device__ float  g_pa[B_SZ * L1D];    // raw features (no bias/clip)
__device__ int    g_dummy;

// ---------------------------------------------------------------------------
// Kernel D: dummy — shifts the ncu -s 5 -c 1 capture slot onto feat_mma.
// ---------------------------------------------------------------------------
__global__ void dummy_kernel() { if (threadIdx.x == 0) g_dummy = 0; }

// ---------------------------------------------------------------------------
// Kernel 0: transpose ft_w (800x1024 -> 1024x800) and split into fp16 hi/lo.
// ---------------------------------------------------------------------------
__global__ __launch_bounds__(256) void prep_bt_kernel(const float* __restrict__ w) {
    __shared__ float ts[32][33];
    int tx = threadIdx.x & 31, ty = threadIdx.x >> 5;   // 32 x 8
    int kbase = blockIdx.y * 32, nbase = blockIdx.x * 32;
#pragma unroll
    for (int i = 0; i < 4; i++)
        ts[ty + i * 8][tx] = w[(size_t)(kbase + ty + i * 8) * L1D + nbase + tx];
    __syncthreads();
#pragma unroll
    for (int i = 0; i < 4; i++) {
        int n = nbase + ty + i * 8;
        int k = kbase + tx;
        float v = ts[tx][ty + i * 8];
        __half h = __float2half_rn(v);
        g_bh[(size_t)n * NF + k] = h;
        g_bl[(size_t)n * NF + k] = __float2half_rn(v - __half2float(h));
    }
}

// ---------------------------------------------------------------------------
// Kernel 1: conv(3x3,s10,p1) + clip + sigmoid gate -> fp16 vals. 256 threads.
// ---------------------------------------------------------------------------
__global__ __launch_bounds__(256) void conv_act_kernel(
    const float* __restrict__ images, const float* __restrict__ conv_w) {
    __shared__ float w[216];
    __shared__ float s[30][3][98];
    int t = threadIdx.x;
    int b = blockIdx.x;
    for (int i = t; i < 216; i += 256) w[i] = conv_w[i];
    for (int i = t; i < 3 * 98; i += 256) s[0][i / 98][i % 98] = 0.f;
    for (int i = t; i < 30 * 3; i += 256) s[i / 3][i % 3][0] = 0.f;
    __syncthreads();

    const float* img = images + (size_t)b * 3 * 96 * 96;
    for (int i = t; i < 29 * 3 * 96; i += 256) {
        int rr = i / 288 + 1; int rem = i - (rr - 1) * 288;
        int c = rem / 96;  int x = rem - c * 96;
        int iy = (rr / 3) * 10 - 1 + rr % 3;
        s[rr][c][x + 1] = __ldg(img + c * 9216 + iy * 96 + x);
    }
    __syncthreads();

    if (t < 100) {
        int oy = t / 10, ox = t - oy * 10;
        float acc[8];
#pragma unroll
        for (int c8 = 0; c8 < 8; c8++) acc[c8] = 0.f;
#pragma unroll
        for (int ky = 0; ky < 3; ky++) {
            const float (*srow)[98] = s[3 * oy + ky];
#pragma unroll
            for (int ic = 0; ic < 3; ic++) {
#pragma unroll
                for (int kx = 0; kx < 3; kx++) {
                    float v = srow[ic][10 * ox + kx];
#pragma unroll
                    for (int c8 = 0; c8 < 8; c8++)
                        acc[c8] = fmaf(v, w[c8 * 27 + ic * 9 + ky * 3 + kx], acc[c8]);
                }
            }
        }
#pragma unroll
        for (int c8 = 0; c8 < 8; c8++) {
            float x  = fminf(fmaxf(acc[c8], -1.f), 1.f);
            float sg = 1.f / (1.f + __expf(-10.f * x));
            float vv = (sg > 0.5f) ? sg : 0.f;
            g_a[(size_t)b * NF + c8 * 100 + t] = __float2half_rn(vv);
        }
    }
}

// ---------------------------------------------------------------------------
// Kernel 2: GEMM = R7's exact best config (BM=BN=64, 128 thr, 4 warps 2x2,
// warp tile 32x32, scalar LDS frags, 2-stage cp.async, 256 CTAs) + K-split
// terms: k<512 -> A*Bh + A*Bl; k>=512 -> A*Bh. Raw partials -> g_pa.
// ---------------------------------------------------------------------------
__device__ __forceinline__ void mma_f16(float* d, const uint32_t* a, const uint32_t* b) {
    asm volatile(
        "mma.sync.aligned.m16n8k16.row.col.f32.f16.f16.f32 "
        "{%0,%1,%2,%3}, {%4,%5,%6,%7}, {%8,%9}, {%0,%1,%2,%3};\n"
        : "+f"(d[0]), "+f"(d[1]), "+f"(d[2]), "+f"(d[3])
        : "r"(a[0]), "r"(a[1]), "r"(a[2]), "r"(a[3]), "r"(b[0]), "r"(b[1]));
}
#define CP16(dst, src) \
    asm volatile("cp.async.ca.shared.global [%0], [%1], 16;\n" :: "r"(dst), "l"(src))

__global__ __launch_bounds__(128) void feat_mma_kernel() {
    __shared__ uint32_t As[2][64][12];
    __shared__ uint32_t Bh[2][64][12];
    __shared__ uint32_t Bl[2][64][12];

    const int t = threadIdx.x, lane = t & 31, wid = t >> 5;
    const int wm = wid >> 1, wn = wid & 1;           // 2 x 2 warps, 32x32 tiles
    const int bm = blockIdx.y * 64, bn = blockIdx.x * 64;

    float acc[2][4][4];
#pragma unroll
    for (int f = 0; f < 2; f++)
#pragma unroll
        for (int j = 0; j < 4; j++)
#pragma unroll
            for (int e = 0; e < 4; e++) acc[f][j][e] = 0.f;

    // staging: each thread 1 chunk of A, Bh, Bl (64 rows x 2 segs each)
    const int row = t >> 1, seg = t & 1;
    const __half* a_src  = g_a  + (size_t)(bm + row) * NF + seg * 8;
    const __half* bh_src = g_bh + (size_t)(bn + row) * NF + seg * 8;
    const __half* bl_src = g_bl + (size_t)(bn + row) * NF + seg * 8;
    uint32_t a_dst[2], bh_dst[2], bl_dst[2];
#pragma unroll
    for (int s2 = 0; s2 < 2; s2++) {
        a_dst[s2]  = (uint32_t)__cvta_generic_to_shared(&As[s2][row][seg * 4]);
        bh_dst[s2] = (uint32_t)__cvta_generic_to_shared(&Bh[s2][row][seg * 4]);
        bl_dst[s2] = (uint32_t)__cvta_generic_to_shared(&Bl[s2][row][seg * 4]);
    }

#define LOAD_STAGE(s2, k0, withBl)                           \
    do {                                                     \
        CP16(a_dst[s2],  a_src  + (k0));                     \
        CP16(bh_dst[s2], bh_src + (k0));                     \
        if (withBl) CP16(bl_dst[s2], bl_src + (k0));         \
        asm volatile("cp.async.commit_group;\n");            \
    } while (0)

    LOAD_STAGE(0, 0, 1);

    const int r0 = wm * 32 + (lane >> 2);
    const int nb = wn * 32 + (lane >> 2);
    const int j0 = lane & 3;

    for (int it = 0; it < NT_IT; it++) {
        int buf = it & 1;
        if (it < NT_IT - 1) {
            LOAD_STAGE(buf ^ 1, (it + 1) * 16, (it + 1) < K2T);
            asm volatile("cp.async.wait_group 1;\n");
        } else {
            asm volatile("cp.async.wait_group 0;\n");
        }
        __syncthreads();

        uint32_t af[2][4];
#pragma unroll
        for (int f = 0; f < 2; f++) {
            int r = r0 + f * 16;
            af[f][0] = As[buf][r][j0];      af[f][1] = As[buf][r + 8][j0];
            af[f][2] = As[buf][r][j0 + 4];  af[f][3] = As[buf][r + 8][j0 + 4];
        }
        uint32_t bhf[4][2];
#pragma unroll
        for (int j = 0; j < 4; j++) {
            int r = nb + j * 8;
            bhf[j][0] = Bh[buf][r][j0]; bhf[j][1] = Bh[buf][r][j0 + 4];
        }
#pragma unroll
        for (int f = 0; f < 2; f++)
#pragma unroll
            for (int j = 0; j < 4; j++)
                mma_f16(acc[f][j], af[f], bhf[j]);

        if (it < K2T) {
            uint32_t blf[4][2];
#pragma unroll
            for (int j = 0; j < 4; j++) {
                int r = nb + j * 8;
                blf[j][0] = Bl[buf][r][j0]; blf[j][1] = Bl[buf][r][j0 + 4];
            }
#pragma unroll
            for (int f = 0; f < 2; f++)
#pragma unroll
                for (int j = 0; j < 4; j++)
                    mma_f16(acc[f][j], af[f], blf[j]);
        }
        __syncthreads();
    }

    // epilogue: raw partial -> g_pa
    const int q = lane & 3, g = lane >> 2;
#pragma unroll
    for (int f = 0; f < 2; f++) {
        int row0 = bm + wm * 32 + f * 16 + g;
#pragma unroll
        for (int j = 0; j < 4; j++) {
            int col = bn + wn * 32 + j * 8 + 2 * q;
            float2 o0 = {acc[f][j][0], acc[f][j][1]};
            float2 o1 = {acc[f][j][2], acc[f][j][3]};
            *(float2*)(g_pa + (size_t)row0 * L1D + col) = o0;
            *(float2*)(g_pa + (size_t)(row0 + 8) * L1D + col) = o1;
        }
    }
}

// ---------------------------------------------------------------------------
// Kernel 3: tail MLP (R12's exact 12.0us version). 2 samples per 512-thr CTA,
// 8 warps per sample. l0[j] = clip(g_pa[j]+ft_b[j], 0, 1), fused.
// ---------------------------------------------------------------------------
__global__ __launch_bounds__(512) void tail_kernel(
    const float* __restrict__ ftb,
    const float* __restrict__ w1, const float* __restrict__ b1,
    const float* __restrict__ w2, const float* __restrict__ b2,
    const float* __restrict__ w3, const float* __restrict__ b3,
    float* __restrict__ out) {
    __shared__ float part[2][8][15];
    __shared__ float h1s[2][15];

    const int t = threadIdx.x, lane = t & 31, wid = t >> 5;
    const int sl = wid >> 3, q = wid & 7;        // sample-local, eighth
    const int sample = blockIdx.x * 2 + sl;
    const float* pa = g_pa + (size_t)sample * L1D;
    const float KCst = 127.f / 128.f;

#define L0(j) fminf(fmaxf(pa[j] + __ldg(ftb + (j)), 0.f), 1.f)

    float c[4];
    if (q < 4) {
#pragma unroll
        for (int i = 0; i < 4; i++) {
            int e = q * 4 + i;
            c[i] = L0(e * 32 + lane) * L0((e + 16) * 32 + lane) * KCst;
        }
    } else {
#pragma unroll
        for (int i = 0; i < 4; i++) {
            int e = (q - 4) * 4 + i;
            c[i] = L0(e * 32 + lane) * KCst;
        }
    }

    float a[15];
#pragma unroll
    for (int o = 0; o < 15; o++) a[o] = 0.f;
    const int jbase = q * 128 + lane;
#pragma unroll
    for (int i = 0; i < 4; i++) {
#pragma unroll
        for (int o = 0; o < 15; o++)
            a[o] = fmaf(c[i], __ldg(w1 + (size_t)o * L1D + jbase + i * 32), a[o]);
    }
#pragma unroll
    for (int s = 16; s; s >>= 1)
#pragma unroll
        for (int o = 0; o < 15; o++)
            a[o] += __shfl_xor_sync(0xffffffffu, a[o], s);
    if (lane < 15) part[sl][q][lane] = a[lane];
    __syncthreads();

    if (q == 0) {
        if (lane < 15) {
            float h = __ldg(b1 + lane);
#pragma unroll
            for (int p = 0; p < 8; p++) h += part[sl][p][lane];
            h1s[sl][lane] = fmaxf(h, 0.f);
        }
        __syncwarp();
        float h2 = __ldg(b2 + lane);
#pragma unroll
        for (int k = 0; k < 15; k++)
            h2 = fmaf(h1s[sl][k], __ldg(w2 + lane * 15 + k), h2);
        h2 = fmaxf(h2, 0.f);
        float ov = h2 * __ldg(w3 + lane);
#pragma unroll
        for (int s = 16; s; s >>= 1) ov += __shfl_xor_sync(0xffffffffu, ov, s);
        if (lane == 0) out[sample] = ov + __ldg(b3);
    }
}

// ---------------------------------------------------------------------------
extern "C" void kernel_launch(void* const* d_in, const int* in_sizes, int n_in,
                              void* d_out, int out_size) {
    const float *images = 0, *conv_w = 0, *ft_w = 0, *ft_b = 0;
    const float *w1 = 0, *b1 = 0, *w2 = 0, *b2 = 0, *w3 = 0, *b3 = 0;

    for (int i = 0; i < n_in; i++) {
        const float* p = (const float*)d_in[i];
        switch (in_sizes[i]) {
            case 28311552: images = p; break;
            case 216:      conv_w = p; break;
            case 819200:   ft_w   = p; break;
            case 1024:     ft_b   = p; break;
            case 15360:    w1     = p; break;
            case 15:       b1     = p; break;
            case 480:      w2     = p; break;
            case 32:       if (!b2) b2 = p; else w3 = p; break;
            case 1:        b3     = p; break;
            default: break;
        }
    }
    float* out = (float*)d_out;

    dummy_kernel<<<1, 32>>>();       // shifts ncu capture slot onto feat_mma

    dim3 gt(L1D / 32, NF / 32);      // 32 x 25
    prep_bt_kernel<<<gt, 256>>>(ft_w);
    conv_act_kernel<<<B_SZ, 256>>>(images, conv_w);

    dim3 g2(L1D / 64, B_SZ / 64);    // 16 x 16 = 256 CTAs
    feat_mma_kernel<<<g2, 128>>>();

    tail_kernel<<<B_SZ / 2, 512>>>(ft_b, w1, b1, w2, b2, w3, b3, out);
}

// round 15
// speedup vs baseline: 1.0584x; 1.0269x over previous
#include <cuda_runtime.h>
#include <cuda_fp16.h>
#include <cstdint>
#include <cstddef>

#define B_SZ 1024
#define NF   800
#define L1D  1024

// Scratch (no allocation allowed — __device__ globals)
__device__ __half g_a[B_SZ * NF];      // vals fp16 (RN), (B,800) row-major
__device__ __half g_bh[L1D * NF];      // ft_w^T hi, (n,k) k-contig
__device__ __half g_bl[L1D * NF];      // ft_w^T lo
__device__ float  g_pa[B_SZ * L1D];    // partial features, K half 0
__device__ float  g_pb[B_SZ * L1D];    // partial features, K half 1
__device__ int    g_dummy;

// ---------------------------------------------------------------------------
// Kernel D: dummy — keeps the ncu -s 5 -c 1 capture slot on feat_mma.
// ---------------------------------------------------------------------------
__global__ void dummy_kernel() { if (threadIdx.x == 0) g_dummy = 0; }

// ---------------------------------------------------------------------------
// Kernel 0: transpose ft_w (800x1024 -> 1024x800) and split into fp16 hi/lo.
// ---------------------------------------------------------------------------
__global__ __launch_bounds__(256) void prep_bt_kernel(const float* __restrict__ w) {
    __shared__ float ts[32][33];
    int tx = threadIdx.x & 31, ty = threadIdx.x >> 5;   // 32 x 8
    int kbase = blockIdx.y * 32, nbase = blockIdx.x * 32;
#pragma unroll
    for (int i = 0; i < 4; i++)
        ts[ty + i * 8][tx] = w[(size_t)(kbase + ty + i * 8) * L1D + nbase + tx];
    __syncthreads();
#pragma unroll
    for (int i = 0; i < 4; i++) {
        int n = nbase + ty + i * 8;
        int k = kbase + tx;
        float v = ts[tx][ty + i * 8];
        __half h = __float2half_rn(v);
        g_bh[(size_t)n * NF + k] = h;
        g_bl[(size_t)n * NF + k] = __float2half_rn(v - __half2float(h));
    }
}

// ---------------------------------------------------------------------------
// Kernel 1: conv(3x3,s10,p1) + clip + sigmoid gate -> fp16 vals. 256 threads.
// ---------------------------------------------------------------------------
__global__ __launch_bounds__(256) void conv_act_kernel(
    const float* __restrict__ images, const float* __restrict__ conv_w) {
    __shared__ float w[216];
    __shared__ float s[30][3][98];
    int t = threadIdx.x;
    int b = blockIdx.x;
    for (int i = t; i < 216; i += 256) w[i] = conv_w[i];
    for (int i = t; i < 3 * 98; i += 256) s[0][i / 98][i % 98] = 0.f;
    for (int i = t; i < 30 * 3; i += 256) s[i / 3][i % 3][0] = 0.f;
    __syncthreads();

    const float* img = images + (size_t)b * 3 * 96 * 96;
    for (int i = t; i < 29 * 3 * 96; i += 256) {
        int rr = i / 288 + 1; int rem = i - (rr - 1) * 288;
        int c = rem / 96;  int x = rem - c * 96;
        int iy = (rr / 3) * 10 - 1 + rr % 3;
        s[rr][c][x + 1] = __ldg(img + c * 9216 + iy * 96 + x);
    }
    __syncthreads();

    if (t < 100) {
        int oy = t / 10, ox = t - oy * 10;
        float acc[8];
#pragma unroll
        for (int c8 = 0; c8 < 8; c8++) acc[c8] = 0.f;
#pragma unroll
        for (int ky = 0; ky < 3; ky++) {
            const float (*srow)[98] = s[3 * oy + ky];
#pragma unroll
            for (int ic = 0; ic < 3; ic++) {
#pragma unroll
                for (int kx = 0; kx < 3; kx++) {
                    float v = srow[ic][10 * ox + kx];
#pragma unroll
                    for (int c8 = 0; c8 < 8; c8++)
                        acc[c8] = fmaf(v, w[c8 * 27 + ic * 9 + ky * 3 + kx], acc[c8]);
                }
            }
        }
#pragma unroll
        for (int c8 = 0; c8 < 8; c8++) {
            float x  = fminf(fmaxf(acc[c8], -1.f), 1.f);
            float sg = 1.f / (1.f + __expf(-10.f * x));
            float vv = (sg > 0.5f) ? sg : 0.f;
            g_a[(size_t)b * NF + c8 * 100 + t] = __float2half_rn(vv);
        }
    }
}

// ---------------------------------------------------------------------------
// Kernel 2: GEMM, K-split across blockIdx.z (2 halves -> 512 CTAs, 13.8
// warps/SM vs 6.9). BM=BN=64, 128 thr, 4 warps (2x2), warp tile 32x32,
// scalar LDS frags, 2-stage cp.async.
//  z=0: k in [0,320), all 2-term (A*Bh + A*Bl)          -> g_pa
//  z=1: k in [320,800), 2-term while k<512, then 1-term -> g_pb
// ---------------------------------------------------------------------------
__device__ __forceinline__ void mma_f16(float* d, const uint32_t* a, const uint32_t* b) {
    asm volatile(
        "mma.sync.aligned.m16n8k16.row.col.f32.f16.f16.f32 "
        "{%0,%1,%2,%3}, {%4,%5,%6,%7}, {%8,%9}, {%0,%1,%2,%3};\n"
        : "+f"(d[0]), "+f"(d[1]), "+f"(d[2]), "+f"(d[3])
        : "r"(a[0]), "r"(a[1]), "r"(a[2]), "r"(a[3]), "r"(b[0]), "r"(b[1]));
}
#define CP16(dst, src) \
    asm volatile("cp.async.ca.shared.global [%0], [%1], 16;\n" :: "r"(dst), "l"(src))

__global__ __launch_bounds__(128) void feat_mma_kernel() {
    __shared__ uint32_t As[2][64][12];
    __shared__ uint32_t Bh[2][64][12];
    __shared__ uint32_t Bl[2][64][12];

    const int t = threadIdx.x, lane = t & 31, wid = t >> 5;
    const int wm = wid >> 1, wn = wid & 1;           // 2 x 2 warps, 32x32 tiles
    const int bm = blockIdx.y * 64, bn = blockIdx.x * 64;
    const int z  = blockIdx.z;
    const int kbeg = z ? 320 : 0;
    const int nit  = z ? 30 : 20;     // iterations of 16
    const int nit2 = z ? 12 : 20;     // iterations with the Bl (2nd) term
    float* dst = z ? g_pb : g_pa;

    float acc[2][4][4];
#pragma unroll
    for (int f = 0; f < 2; f++)
#pragma unroll
        for (int j = 0; j < 4; j++)
#pragma unroll
            for (int e = 0; e < 4; e++) acc[f][j][e] = 0.f;

    // staging: each thread 1 chunk of A, Bh, Bl (64 rows x 2 segs each)
    const int row = t >> 1, seg = t & 1;
    const __half* a_src  = g_a  + (size_t)(bm + row) * NF + kbeg + seg * 8;
    const __half* bh_src = g_bh + (size_t)(bn + row) * NF + kbeg + seg * 8;
    const __half* bl_src = g_bl + (size_t)(bn + row) * NF + kbeg + seg * 8;
    uint32_t a_dst[2], bh_dst[2], bl_dst[2];
#pragma unroll
    for (int s2 = 0; s2 < 2; s2++) {
        a_dst[s2]  = (uint32_t)__cvta_generic_to_shared(&As[s2][row][seg * 4]);
        bh_dst[s2] = (uint32_t)__cvta_generic_to_shared(&Bh[s2][row][seg * 4]);
        bl_dst[s2] = (uint32_t)__cvta_generic_to_shared(&Bl[s2][row][seg * 4]);
    }

#define LOAD_STAGE(s2, k0, withBl)                           \
    do {                                                     \
        CP16(a_dst[s2],  a_src  + (k0));                     \
        CP16(bh_dst[s2], bh_src + (k0));                     \
        if (withBl) CP16(bl_dst[s2], bl_src + (k0));         \
        asm volatile("cp.async.commit_group;\n");            \
    } while (0)

    LOAD_STAGE(0, 0, 1);

    const int r0 = wm * 32 + (lane >> 2);
    const int nb = wn * 32 + (lane >> 2);
    const int j0 = lane & 3;

    for (int it = 0; it < nit; it++) {
        int buf = it & 1;
        if (it < nit - 1) {
            LOAD_STAGE(buf ^ 1, (it + 1) * 16, (it + 1) < nit2);
            asm volatile("cp.async.wait_group 1;\n");
        } else {
            asm volatile("cp.async.wait_group 0;\n");
        }
        __syncthreads();

        uint32_t af[2][4];
#pragma unroll
        for (int f = 0; f < 2; f++) {
            int r = r0 + f * 16;
            af[f][0] = As[buf][r][j0];      af[f][1] = As[buf][r + 8][j0];
            af[f][2] = As[buf][r][j0 + 4];  af[f][3] = As[buf][r + 8][j0 + 4];
        }
        uint32_t bhf[4][2];
#pragma unroll
        for (int j = 0; j < 4; j++) {
            int r = nb + j * 8;
            bhf[j][0] = Bh[buf][r][j0]; bhf[j][1] = Bh[buf][r][j0 + 4];
        }
#pragma unroll
        for (int f = 0; f < 2; f++)
#pragma unroll
            for (int j = 0; j < 4; j++)
                mma_f16(acc[f][j], af[f], bhf[j]);

        if (it < nit2) {
            uint32_t blf[4][2];
#pragma unroll
            for (int j = 0; j < 4; j++) {
                int r = nb + j * 8;
                blf[j][0] = Bl[buf][r][j0]; blf[j][1] = Bl[buf][r][j0 + 4];
            }
#pragma unroll
            for (int f = 0; f < 2; f++)
#pragma unroll
                for (int j = 0; j < 4; j++)
                    mma_f16(acc[f][j], af[f], blf[j]);
        }
        __syncthreads();
    }

    // epilogue: raw partial -> dst
    const int q = lane & 3, g = lane >> 2;
#pragma unroll
    for (int f = 0; f < 2; f++) {
        int row0 = bm + wm * 32 + f * 16 + g;
#pragma unroll
        for (int j = 0; j < 4; j++) {
            int col = bn + wn * 32 + j * 8 + 2 * q;
            float2 o0 = {acc[f][j][0], acc[f][j][1]};
            float2 o1 = {acc[f][j][2], acc[f][j][3]};
            *(float2*)(dst + (size_t)row0 * L1D + col) = o0;
            *(float2*)(dst + (size_t)(row0 + 8) * L1D + col) = o1;
        }
    }
}

// ---------------------------------------------------------------------------
// Kernel 3: tail MLP. 2 samples per 512-thr CTA, 8 warps per sample.
// l0[j] = clip(g_pa[j] + g_pb[j] + ft_b[j], 0, 1), fused.
// ---------------------------------------------------------------------------
__global__ __launch_bounds__(512) void tail_kernel(
    const float* __restrict__ ftb,
    const float* __restrict__ w1, const float* __restrict__ b1,
    const float* __restrict__ w2, const float* __restrict__ b2,
    const float* __restrict__ w3, const float* __restrict__ b3,
    float* __restrict__ out) {
    __shared__ float part[2][8][15];
    __shared__ float h1s[2][15];

    const int t = threadIdx.x, lane = t & 31, wid = t >> 5;
    const int sl = wid >> 3, q = wid & 7;        // sample-local, eighth
    const int sample = blockIdx.x * 2 + sl;
    const float* pa = g_pa + (size_t)sample * L1D;
    const float* pb = g_pb + (size_t)sample * L1D;
    const float KCst = 127.f / 128.f;

#define L0(j) fminf(fmaxf(pa[j] + pb[j] + __ldg(ftb + (j)), 0.f), 1.f)

    float c[4];
    if (q < 4) {
#pragma unroll
        for (int i = 0; i < 4; i++) {
            int e = q * 4 + i;
            c[i] = L0(e * 32 + lane) * L0((e + 16) * 32 + lane) * KCst;
        }
    } else {
#pragma unroll
        for (int i = 0; i < 4; i++) {
            int e = (q - 4) * 4 + i;
            c[i] = L0(e * 32 + lane) * KCst;
        }
    }

    float a[15];
#pragma unroll
    for (int o = 0; o < 15; o++) a[o] = 0.f;
    const int jbase = q * 128 + lane;
#pragma unroll
    for (int i = 0; i < 4; i++) {
#pragma unroll
        for (int o = 0; o < 15; o++)
            a[o] = fmaf(c[i], __ldg(w1 + (size_t)o * L1D + jbase + i * 32), a[o]);
    }
#pragma unroll
    for (int s = 16; s; s >>= 1)
#pragma unroll
        for (int o = 0; o < 15; o++)
            a[o] += __shfl_xor_sync(0xffffffffu, a[o], s);
    if (lane < 15) part[sl][q][lane] = a[lane];
    __syncthreads();

    if (q == 0) {
        if (lane < 15) {
            float h = __ldg(b1 + lane);
#pragma unroll
            for (int p = 0; p < 8; p++) h += part[sl][p][lane];
            h1s[sl][lane] = fmaxf(h, 0.f);
        }
        __syncwarp();
        float h2 = __ldg(b2 + lane);
#pragma unroll
        for (int k = 0; k < 15; k++)
            h2 = fmaf(h1s[sl][k], __ldg(w2 + lane * 15 + k), h2);
        h2 = fmaxf(h2, 0.f);
        float ov = h2 * __ldg(w3 + lane);
#pragma unroll
        for (int s = 16; s; s >>= 1) ov += __shfl_xor_sync(0xffffffffu, ov, s);
        if (lane == 0) out[sample] = ov + __ldg(b3);
    }
}

// ---------------------------------------------------------------------------
extern "C" void kernel_launch(void* const* d_in, const int* in_sizes, int n_in,
                              void* d_out, int out_size) {
    const float *images = 0, *conv_w = 0, *ft_w = 0, *ft_b = 0;
    const float *w1 = 0, *b1 = 0, *w2 = 0, *b2 = 0, *w3 = 0, *b3 = 0;

    for (int i = 0; i < n_in; i++) {
        const float* p = (const float*)d_in[i];
        switch (in_sizes[i]) {
            case 28311552: images = p; break;
            case 216:      conv_w = p; break;
            case 819200:   ft_w   = p; break;
            case 1024:     ft_b   = p; break;
            case 15360:    w1     = p; break;
            case 15:       b1     = p; break;
            case 480:      w2     = p; break;
            case 32:       if (!b2) b2 = p; else w3 = p; break;
            case 1:        b3     = p; break;
            default: break;
        }
    }
    float* out = (float*)d_out;

    dummy_kernel<<<1, 32>>>();       // keeps ncu capture slot on feat_mma

    dim3 gt(L1D / 32, NF / 32);      // 32 x 25
    prep_bt_kernel<<<gt, 256>>>(ft_w);
    conv_act_kernel<<<B_SZ, 256>>>(images, conv_w);

    dim3 g2(L1D / 64, B_SZ / 64, 2); // 16 x 16 x 2 = 512 CTAs
    feat_mma_kernel<<<g2, 128>>>();

    tail_kernel<<<B_SZ / 2, 512>>>(ft_b, w1, b1, w2, b2, w3, b3, out);
}

// round 16
// speedup vs baseline: 1.1978x; 1.1317x over previous
#include <cuda_runtime.h>
#include <cuda_fp16.h>
#include <cstdint>
#include <cstddef>

#define B_SZ 1024
#define NF   800
#define L1D  1024

// Scratch (no allocation allowed — __device__ globals)
__device__ __half g_a[B_SZ * NF];      // vals fp16 (RN), (B,800) row-major
__device__ __half g_bh[L1D * NF];      // ft_w^T hi, (n,k) k-contig
__device__ __half g_bl[L1D * NF];      // ft_w^T lo
__device__ float  g_pa[B_SZ * L1D];    // partial features, K half 0
__device__ float  g_pb[B_SZ * L1D];    // partial features, K half 1
__device__ int    g_dummy;

// ---------------------------------------------------------------------------
// Kernel D: dummy — keeps the ncu -s 5 -c 1 capture slot on feat_mma.
// ---------------------------------------------------------------------------
__global__ void dummy_kernel() { if (threadIdx.x == 0) g_dummy = 0; }

// ---------------------------------------------------------------------------
// Kernel 0: transpose ft_w (800x1024 -> 1024x800) and split into fp16 hi/lo.
// ---------------------------------------------------------------------------
__global__ __launch_bounds__(256) void prep_bt_kernel(const float* __restrict__ w) {
    __shared__ float ts[32][33];
    int tx = threadIdx.x & 31, ty = threadIdx.x >> 5;   // 32 x 8
    int kbase = blockIdx.y * 32, nbase = blockIdx.x * 32;
#pragma unroll
    for (int i = 0; i < 4; i++)
        ts[ty + i * 8][tx] = w[(size_t)(kbase + ty + i * 8) * L1D + nbase + tx];
    __syncthreads();
#pragma unroll
    for (int i = 0; i < 4; i++) {
        int n = nbase + ty + i * 8;
        int k = kbase + tx;
        float v = ts[tx][ty + i * 8];
        __half h = __float2half_rn(v);
        g_bh[(size_t)n * NF + k] = h;
        g_bl[(size_t)n * NF + k] = __float2half_rn(v - __half2float(h));
    }
}

// ---------------------------------------------------------------------------
// Kernel 1: conv(3x3,s10,p1) + clip + sigmoid gate -> fp16 vals.
// float4 staging: 29 rows x 3 ch x 24 float4 = 2088 loads per image.
// ---------------------------------------------------------------------------
__global__ __launch_bounds__(256) void conv_act_kernel(
    const float* __restrict__ images, const float* __restrict__ conv_w) {
    __shared__ float w[216];
    __shared__ float s[30][3][98];
    int t = threadIdx.x;
    int b = blockIdx.x;
    for (int i = t; i < 216; i += 256) w[i] = conv_w[i];
    for (int i = t; i < 3 * 98; i += 256) s[0][i / 98][i % 98] = 0.f;
    for (int i = t; i < 30 * 3; i += 256) s[i / 3][i % 3][0] = 0.f;
    __syncthreads();

    const float* img = images + (size_t)b * 3 * 96 * 96;
    // i -> (rr-1, c, x4): rr-1 = i/72, c = (i%72)/24, x4 = i%24
    for (int i = t; i < 29 * 3 * 24; i += 256) {
        int rm = i / 72;  int rem = i - rm * 72;
        int c  = rem / 24; int x4 = rem - c * 24;
        int rr = rm + 1;
        int iy = (rr / 3) * 10 - 1 + rr % 3;
        float4 v = __ldg((const float4*)(img + c * 9216 + iy * 96 + x4 * 4));
        float* d = &s[rr][c][x4 * 4 + 1];
        d[0] = v.x; d[1] = v.y; d[2] = v.z; d[3] = v.w;
    }
    __syncthreads();

    if (t < 100) {
        int oy = t / 10, ox = t - oy * 10;
        float acc[8];
#pragma unroll
        for (int c8 = 0; c8 < 8; c8++) acc[c8] = 0.f;
#pragma unroll
        for (int ky = 0; ky < 3; ky++) {
            const float (*srow)[98] = s[3 * oy + ky];
#pragma unroll
            for (int ic = 0; ic < 3; ic++) {
#pragma unroll
                for (int kx = 0; kx < 3; kx++) {
                    float v = srow[ic][10 * ox + kx];
#pragma unroll
                    for (int c8 = 0; c8 < 8; c8++)
                        acc[c8] = fmaf(v, w[c8 * 27 + ic * 9 + ky * 3 + kx], acc[c8]);
                }
            }
        }
#pragma unroll
        for (int c8 = 0; c8 < 8; c8++) {
            float x  = fminf(fmaxf(acc[c8], -1.f), 1.f);
            float sg = 1.f / (1.f + __expf(-10.f * x));
            float vv = (sg > 0.5f) ? sg : 0.f;
            g_a[(size_t)b * NF + c8 * 100 + t] = __float2half_rn(vv);
        }
    }
}

// ---------------------------------------------------------------------------
// Kernel 2: GEMM, K-split (z=2) AND 8 warps/CTA -> 27.7 warps/SM.
// BM=BN=64, 256 thr, warps 2m x 4n, warp tile 32x16, scalar LDS frags,
// 2-stage cp.async.
//  z=0: k in [0,320), all 2-term (A*Bh + A*Bl)          -> g_pa
//  z=1: k in [320,800), 2-term while k<512, then 1-term -> g_pb
// ---------------------------------------------------------------------------
__device__ __forceinline__ void mma_f16(float* d, const uint32_t* a, const uint32_t* b) {
    asm volatile(
        "mma.sync.aligned.m16n8k16.row.col.f32.f16.f16.f32 "
        "{%0,%1,%2,%3}, {%4,%5,%6,%7}, {%8,%9}, {%0,%1,%2,%3};\n"
        : "+f"(d[0]), "+f"(d[1]), "+f"(d[2]), "+f"(d[3])
        : "r"(a[0]), "r"(a[1]), "r"(a[2]), "r"(a[3]), "r"(b[0]), "r"(b[1]));
}
#define CP16(dst, src) \
    asm volatile("cp.async.ca.shared.global [%0], [%1], 16;\n" :: "r"(dst), "l"(src))

__global__ __launch_bounds__(256) void feat_mma_kernel() {
    __shared__ uint32_t As[2][64][12];
    __shared__ uint32_t Bh[2][64][12];
    __shared__ uint32_t Bl[2][64][12];

    const int t = threadIdx.x, lane = t & 31, wid = t >> 5;
    const int wm = wid >> 2, wn = wid & 3;           // 2 x 4 warps, 32x16 tiles
    const int bm = blockIdx.y * 64, bn = blockIdx.x * 64;
    const int z  = blockIdx.z;
    const int kbeg = z ? 320 : 0;
    const int nit  = z ? 30 : 20;     // iterations of 16
    const int nit2 = z ? 12 : 20;     // iterations with the Bl (2nd) term
    float* dst = z ? g_pb : g_pa;

    float acc[2][2][4];
#pragma unroll
    for (int f = 0; f < 2; f++)
#pragma unroll
        for (int j = 0; j < 2; j++)
#pragma unroll
            for (int e = 0; e < 4; e++) acc[f][j][e] = 0.f;

    // staging: t<128 -> A chunk (+Bl chunk); t>=128 -> Bh chunk.
    const int arow = (t & 127) >> 1, aseg = t & 1;
    const __half* a_src  = g_a  + (size_t)(bm + arow) * NF + kbeg + aseg * 8;
    const __half* bh_src = g_bh + (size_t)(bn + arow) * NF + kbeg + aseg * 8;
    const __half* bl_src = g_bl + (size_t)(bn + arow) * NF + kbeg + aseg * 8;
    uint32_t a_dst[2], bh_dst[2], bl_dst[2];
#pragma unroll
    for (int s2 = 0; s2 < 2; s2++) {
        a_dst[s2]  = (uint32_t)__cvta_generic_to_shared(&As[s2][arow][aseg * 4]);
        bh_dst[s2] = (uint32_t)__cvta_generic_to_shared(&Bh[s2][arow][aseg * 4]);
        bl_dst[s2] = (uint32_t)__cvta_generic_to_shared(&Bl[s2][arow][aseg * 4]);
    }

#define LOAD_STAGE(s2, k0, withBl)                               \
    do {                                                         \
        if (t < 128) {                                           \
            CP16(a_dst[s2], a_src + (k0));                       \
            if (withBl) CP16(bl_dst[s2], bl_src + (k0));         \
        } else {                                                 \
            CP16(bh_dst[s2], bh_src + (k0));                     \
        }                                                        \
        asm volatile("cp.async.commit_group;\n");                \
    } while (0)

    LOAD_STAGE(0, 0, 1);

    const int r0 = wm * 32 + (lane >> 2);
    const int nb = wn * 16 + (lane >> 2);
    const int j0 = lane & 3;

    for (int it = 0; it < nit; it++) {
        int buf = it & 1;
        if (it < nit - 1) {
            LOAD_STAGE(buf ^ 1, (it + 1) * 16, (it + 1) < nit2);
            asm volatile("cp.async.wait_group 1;\n");
        } else {
            asm volatile("cp.async.wait_group 0;\n");
        }
        __syncthreads();

        uint32_t af[2][4];
#pragma unroll
        for (int f = 0; f < 2; f++) {
            int r = r0 + f * 16;
            af[f][0] = As[buf][r][j0];      af[f][1] = As[buf][r + 8][j0];
            af[f][2] = As[buf][r][j0 + 4];  af[f][3] = As[buf][r + 8][j0 + 4];
        }
        uint32_t bhf[2][2];
#pragma unroll
        for (int j = 0; j < 2; j++) {
            int r = nb + j * 8;
            bhf[j][0] = Bh[buf][r][j0]; bhf[j][1] = Bh[buf][r][j0 + 4];
        }
#pragma unroll
        for (int f = 0; f < 2; f++)
#pragma unroll
            for (int j = 0; j < 2; j++)
                mma_f16(acc[f][j], af[f], bhf[j]);

        if (it < nit2) {
            uint32_t blf[2][2];
#pragma unroll
            for (int j = 0; j < 2; j++) {
                int r = nb + j * 8;
                blf[j][0] = Bl[buf][r][j0]; blf[j][1] = Bl[buf][r][j0 + 4];
            }
#pragma unroll
            for (int f = 0; f < 2; f++)
#pragma unroll
                for (int j = 0; j < 2; j++)
                    mma_f16(acc[f][j], af[f], blf[j]);
        }
        __syncthreads();
    }

    // epilogue: raw partial -> dst
    const int q = lane & 3, g = lane >> 2;
#pragma unroll
    for (int f = 0; f < 2; f++) {
        int row0 = bm + wm * 32 + f * 16 + g;
#pragma unroll
        for (int j = 0; j < 2; j++) {
            int col = bn + wn * 16 + j * 8 + 2 * q;
            float2 o0 = {acc[f][j][0], acc[f][j][1]};
            float2 o1 = {acc[f][j][2], acc[f][j][3]};
            *(float2*)(dst + (size_t)row0 * L1D + col) = o0;
            *(float2*)(dst + (size_t)(row0 + 8) * L1D + col) = o1;
        }
    }
}

// ---------------------------------------------------------------------------
// Kernel 3: tail MLP. 2 samples per 512-thr CTA, 8 warps per sample.
// l0[j] = clip(g_pa[j] + g_pb[j] + ft_b[j], 0, 1), fused.
// ---------------------------------------------------------------------------
__global__ __launch_bounds__(512) void tail_kernel(
    const float* __restrict__ ftb,
    const float* __restrict__ w1, const float* __restrict__ b1,
    const float* __restrict__ w2, const float* __restrict__ b2,
    const float* __restrict__ w3, const float* __restrict__ b3,
    float* __restrict__ out) {
    __shared__ float part[2][8][15];
    __shared__ float h1s[2][15];

    const int t = threadIdx.x, lane = t & 31, wid = t >> 5;
    const int sl = wid >> 3, q = wid & 7;        // sample-local, eighth
    const int sample = blockIdx.x * 2 + sl;
    const float* pa = g_pa + (size_t)sample * L1D;
    const float* pb = g_pb + (size_t)sample * L1D;
    const float KCst = 127.f / 128.f;

#define L0(j) fminf(fmaxf(pa[j] + pb[j] + __ldg(ftb + (j)), 0.f), 1.f)

    float c[4];
    if (q < 4) {
#pragma unroll
        for (int i = 0; i < 4; i++) {
            int e = q * 4 + i;
            c[i] = L0(e * 32 + lane) * L0((e + 16) * 32 + lane) * KCst;
        }
    } else {
#pragma unroll
        for (int i = 0; i < 4; i++) {
            int e = (q - 4) * 4 + i;
            c[i] = L0(e * 32 + lane) * KCst;
        }
    }

    float a[15];
#pragma unroll
    for (int o = 0; o < 15; o++) a[o] = 0.f;
    const int jbase = q * 128 + lane;
#pragma unroll
    for (int i = 0; i < 4; i++) {
#pragma unroll
        for (int o = 0; o < 15; o++)
            a[o] = fmaf(c[i], __ldg(w1 + (size_t)o * L1D + jbase + i * 32), a[o]);
    }
#pragma unroll
    for (int s = 16; s; s >>= 1)
#pragma unroll
        for (int o = 0; o < 15; o++)
            a[o] += __shfl_xor_sync(0xffffffffu, a[o], s);
    if (lane < 15) part[sl][q][lane] = a[lane];
    __syncthreads();

    if (q == 0) {
        if (lane < 15) {
            float h = __ldg(b1 + lane);
#pragma unroll
            for (int p = 0; p < 8; p++) h += part[sl][p][lane];
            h1s[sl][lane] = fmaxf(h, 0.f);
        }
        __syncwarp();
        float h2 = __ldg(b2 + lane);
#pragma unroll
        for (int k = 0; k < 15; k++)
            h2 = fmaf(h1s[sl][k], __ldg(w2 + lane * 15 + k), h2);
        h2 = fmaxf(h2, 0.f);
        float ov = h2 * __ldg(w3 + lane);
#pragma unroll
        for (int s = 16; s; s >>= 1) ov += __shfl_xor_sync(0xffffffffu, ov, s);
        if (lane == 0) out[sample] = ov + __ldg(b3);
    }
}

// ---------------------------------------------------------------------------
extern "C" void kernel_launch(void* const* d_in, const int* in_sizes, int n_in,
                              void* d_out, int out_size) {
    const float *images = 0, *conv_w = 0, *ft_w = 0, *ft_b = 0;
    const float *w1 = 0, *b1 = 0, *w2 = 0, *b2 = 0, *w3 = 0, *b3 = 0;

    for (int i = 0; i < n_in; i++) {
        const float* p = (const float*)d_in[i];
        switch (in_sizes[i]) {
            case 28311552: images = p; break;
            case 216:      conv_w = p; break;
            case 819200:   ft_w   = p; break;
            case 1024:     ft_b   = p; break;
            case 15360:    w1     = p; break;
            case 15:       b1     = p; break;
            case 480:      w2     = p; break;
            case 32:       if (!b2) b2 = p; else w3 = p; break;
            case 1:        b3     = p; break;
            default: break;
        }
    }
    float* out = (float*)d_out;

    dummy_kernel<<<1, 32>>>();       // keeps ncu capture slot on feat_mma

    dim3 gt(L1D / 32, NF / 32);      // 32 x 25
    prep_bt_kernel<<<gt, 256>>>(ft_w);
    conv_act_kernel<<<B_SZ, 256>>>(images, conv_w);

    dim3 g2(L1D / 64, B_SZ / 64, 2); // 16 x 16 x 2 = 512 CTAs
    feat_mma_kernel<<<g2, 256>>>();

    tail_kernel<<<B_SZ / 2, 512>>>(ft_b, w1, b1, w2, b2, w3, b3, out);
}

// round 17
// speedup vs baseline: 1.2833x; 1.0714x over previous
#include <cuda_runtime.h>
#include <cuda_fp16.h>
#include <cstdint>
#include <cstddef>

#define B_SZ 1024
#define NF   800
#define L1D  1024

// Scratch (no allocation allowed — __device__ globals)
__device__ __half g_a[B_SZ * NF];      // vals fp16 (RN), (B,800) row-major
__device__ __half g_bh[L1D * NF];      // ft_w^T fp16 (RN), (n,k) k-contig
__device__ float  g_pa[B_SZ * L1D];    // partial features, K half 0
__device__ float  g_pb[B_SZ * L1D];    // partial features, K half 1
__device__ int    g_dummy;

// ---------------------------------------------------------------------------
// Kernel D: dummy — keeps the ncu -s 5 -c 1 capture slot on feat_mma.
// ---------------------------------------------------------------------------
__global__ void dummy_kernel() { if (threadIdx.x == 0) g_dummy = 0; }

// ---------------------------------------------------------------------------
// Kernel 0: transpose ft_w (800x1024 -> 1024x800), fp16 RN.
// ---------------------------------------------------------------------------
__global__ __launch_bounds__(256) void prep_bt_kernel(const float* __restrict__ w) {
    __shared__ float ts[32][33];
    int tx = threadIdx.x & 31, ty = threadIdx.x >> 5;   // 32 x 8
    int kbase = blockIdx.y * 32, nbase = blockIdx.x * 32;
#pragma unroll
    for (int i = 0; i < 4; i++)
        ts[ty + i * 8][tx] = w[(size_t)(kbase + ty + i * 8) * L1D + nbase + tx];
    __syncthreads();
#pragma unroll
    for (int i = 0; i < 4; i++) {
        int n = nbase + ty + i * 8;
        int k = kbase + tx;
        g_bh[(size_t)n * NF + k] = __float2half_rn(ts[tx][ty + i * 8]);
    }
}

// ---------------------------------------------------------------------------
// Kernel 1: conv(3x3,s10,p1) + clip + sigmoid gate -> fp16 vals.
// float4 staging: 29 rows x 3 ch x 24 float4 = 2088 loads per image.
// ---------------------------------------------------------------------------
__global__ __launch_bounds__(256) void conv_act_kernel(
    const float* __restrict__ images, const float* __restrict__ conv_w) {
    __shared__ float w[216];
    __shared__ float s[30][3][98];
    int t = threadIdx.x;
    int b = blockIdx.x;
    for (int i = t; i < 216; i += 256) w[i] = conv_w[i];
    for (int i = t; i < 3 * 98; i += 256) s[0][i / 98][i % 98] = 0.f;
    for (int i = t; i < 30 * 3; i += 256) s[i / 3][i % 3][0] = 0.f;
    __syncthreads();

    const float* img = images + (size_t)b * 3 * 96 * 96;
    for (int i = t; i < 29 * 3 * 24; i += 256) {
        int rm = i / 72;  int rem = i - rm * 72;
        int c  = rem / 24; int x4 = rem - c * 24;
        int rr = rm + 1;
        int iy = (rr / 3) * 10 - 1 + rr % 3;
        float4 v = __ldg((const float4*)(img + c * 9216 + iy * 96 + x4 * 4));
        float* d = &s[rr][c][x4 * 4 + 1];
        d[0] = v.x; d[1] = v.y; d[2] = v.z; d[3] = v.w;
    }
    __syncthreads();

    if (t < 100) {
        int oy = t / 10, ox = t - oy * 10;
        float acc[8];
#pragma unroll
        for (int c8 = 0; c8 < 8; c8++) acc[c8] = 0.f;
#pragma unroll
        for (int ky = 0; ky < 3; ky++) {
            const float (*srow)[98] = s[3 * oy + ky];
#pragma unroll
            for (int ic = 0; ic < 3; ic++) {
#pragma unroll
                for (int kx = 0; kx < 3; kx++) {
                    float v = srow[ic][10 * ox + kx];
#pragma unroll
                    for (int c8 = 0; c8 < 8; c8++)
                        acc[c8] = fmaf(v, w[c8 * 27 + ic * 9 + ky * 3 + kx], acc[c8]);
                }
            }
        }
#pragma unroll
        for (int c8 = 0; c8 < 8; c8++) {
            float x  = fminf(fmaxf(acc[c8], -1.f), 1.f);
            float sg = 1.f / (1.f + __expf(-10.f * x));
            float vv = (sg > 0.5f) ? sg : 0.f;
            g_a[(size_t)b * NF + c8 * 100 + t] = __float2half_rn(vv);
        }
    }
}

// ---------------------------------------------------------------------------
// Kernel 2: GEMM, single-term fp16 (D = A*B, fp32 accum). Chip HMMA rate is
// the hard binder (~25K mma/us invariant), so minimize mma count: 409K total.
// K-split z=2 balanced (25 iters each), BM=BN=64, 256 thr, 8 warps (2m x 4n),
// warp tile 32x16, scalar LDS frags, 2-stage cp.async.
//  z=0: k in [0,400)   -> g_pa ;  z=1: k in [400,800) -> g_pb
// ---------------------------------------------------------------------------
__device__ __forceinline__ void mma_f16(float* d, const uint32_t* a, const uint32_t* b) {
    asm volatile(
        "mma.sync.aligned.m16n8k16.row.col.f32.f16.f16.f32 "
        "{%0,%1,%2,%3}, {%4,%5,%6,%7}, {%8,%9}, {%0,%1,%2,%3};\n"
        : "+f"(d[0]), "+f"(d[1]), "+f"(d[2]), "+f"(d[3])
        : "r"(a[0]), "r"(a[1]), "r"(a[2]), "r"(a[3]), "r"(b[0]), "r"(b[1]));
}
#define CP16(dst, src) \
    asm volatile("cp.async.ca.shared.global [%0], [%1], 16;\n" :: "r"(dst), "l"(src))

#define NIT 25   // k-iterations of 16 per z-half

__global__ __launch_bounds__(256) void feat_mma_kernel() {
    __shared__ uint32_t As[2][64][12];
    __shared__ uint32_t Bs[2][64][12];

    const int t = threadIdx.x, lane = t & 31, wid = t >> 5;
    const int wm = wid >> 2, wn = wid & 3;           // 2 x 4 warps, 32x16 tiles
    const int bm = blockIdx.y * 64, bn = blockIdx.x * 64;
    const int z  = blockIdx.z;
    const int kbeg = z * 400;
    float* dst = z ? g_pb : g_pa;

    float acc[2][2][4];
#pragma unroll
    for (int f = 0; f < 2; f++)
#pragma unroll
        for (int j = 0; j < 2; j++)
#pragma unroll
            for (int e = 0; e < 4; e++) acc[f][j][e] = 0.f;

    // staging: t<128 -> A chunk; t>=128 -> B chunk (64 rows x 2 segs each)
    const int row = (t & 127) >> 1, seg = t & 1;
    const __half* src = (t < 128)
        ? g_a  + (size_t)(bm + row) * NF + kbeg + seg * 8
        : g_bh + (size_t)(bn + row) * NF + kbeg + seg * 8;
    uint32_t sdst[2];
#pragma unroll
    for (int s2 = 0; s2 < 2; s2++)
        sdst[s2] = (uint32_t)__cvta_generic_to_shared(
            (t < 128) ? &As[s2][row][seg * 4] : &Bs[s2][row][seg * 4]);

#define LOAD_STAGE(s2, k0)                                   \
    do {                                                     \
        CP16(sdst[s2], src + (k0));                          \
        asm volatile("cp.async.commit_group;\n");            \
    } while (0)

    LOAD_STAGE(0, 0);

    const int r0 = wm * 32 + (lane >> 2);
    const int nb = wn * 16 + (lane >> 2);
    const int j0 = lane & 3;

    for (int it = 0; it < NIT; it++) {
        int buf = it & 1;
        if (it < NIT - 1) {
            LOAD_STAGE(buf ^ 1, (it + 1) * 16);
            asm volatile("cp.async.wait_group 1;\n");
        } else {
            asm volatile("cp.async.wait_group 0;\n");
        }
        __syncthreads();

        uint32_t af[2][4];
#pragma unroll
        for (int f = 0; f < 2; f++) {
            int r = r0 + f * 16;
            af[f][0] = As[buf][r][j0];      af[f][1] = As[buf][r + 8][j0];
            af[f][2] = As[buf][r][j0 + 4];  af[f][3] = As[buf][r + 8][j0 + 4];
        }
        uint32_t bf[2][2];
#pragma unroll
        for (int j = 0; j < 2; j++) {
            int r = nb + j * 8;
            bf[j][0] = Bs[buf][r][j0]; bf[j][1] = Bs[buf][r][j0 + 4];
        }
#pragma unroll
        for (int f = 0; f < 2; f++)
#pragma unroll
            for (int j = 0; j < 2; j++)
                mma_f16(acc[f][j], af[f], bf[j]);
        __syncthreads();
    }

    // epilogue: raw partial -> dst
    const int q = lane & 3, g = lane >> 2;
#pragma unroll
    for (int f = 0; f < 2; f++) {
        int row0 = bm + wm * 32 + f * 16 + g;
#pragma unroll
        for (int j = 0; j < 2; j++) {
            int col = bn + wn * 16 + j * 8 + 2 * q;
            float2 o0 = {acc[f][j][0], acc[f][j][1]};
            float2 o1 = {acc[f][j][2], acc[f][j][3]};
            *(float2*)(dst + (size_t)row0 * L1D + col) = o0;
            *(float2*)(dst + (size_t)(row0 + 8) * L1D + col) = o1;
        }
    }
}

// ---------------------------------------------------------------------------
// Kernel 3: tail MLP. 2 samples per 512-thr CTA, 8 warps per sample.
// l0[j] = clip(g_pa[j] + g_pb[j] + ft_b[j], 0, 1), fused.
// ---------------------------------------------------------------------------
__global__ __launch_bounds__(512) void tail_kernel(
    const float* __restrict__ ftb,
    const float* __restrict__ w1, const float* __restrict__ b1,
    const float* __restrict__ w2, const float* __restrict__ b2,
    const float* __restrict__ w3, const float* __restrict__ b3,
    float* __restrict__ out) {
    __shared__ float part[2][8][15];
    __shared__ float h1s[2][15];

    const int t = threadIdx.x, lane = t & 31, wid = t >> 5;
    const int sl = wid >> 3, q = wid & 7;        // sample-local, eighth
    const int sample = blockIdx.x * 2 + sl;
    const float* pa = g_pa + (size_t)sample * L1D;
    const float* pb = g_pb + (size_t)sample * L1D;
    const float KCst = 127.f / 128.f;

#define L0(j) fminf(fmaxf(pa[j] + pb[j] + __ldg(ftb + (j)), 0.f), 1.f)

    float c[4];
    if (q < 4) {
#pragma unroll
        for (int i = 0; i < 4; i++) {
            int e = q * 4 + i;
            c[i] = L0(e * 32 + lane) * L0((e + 16) * 32 + lane) * KCst;
        }
    } else {
#pragma unroll
        for (int i = 0; i < 4; i++) {
            int e = (q - 4) * 4 + i;
            c[i] = L0(e * 32 + lane) * KCst;
        }
    }

    float a[15];
#pragma unroll
    for (int o = 0; o < 15; o++) a[o] = 0.f;
    const int jbase = q * 128 + lane;
#pragma unroll
    for (int i = 0; i < 4; i++) {
#pragma unroll
        for (int o = 0; o < 15; o++)
            a[o] = fmaf(c[i], __ldg(w1 + (size_t)o * L1D + jbase + i * 32), a[o]);
    }
#pragma unroll
    for (int s = 16; s; s >>= 1)
#pragma unroll
        for (int o = 0; o < 15; o++)
            a[o] += __shfl_xor_sync(0xffffffffu, a[o], s);
    if (lane < 15) part[sl][q][lane] = a[lane];
    __syncthreads();

    if (q == 0) {
        if (lane < 15) {
            float h = __ldg(b1 + lane);
#pragma unroll
            for (int p = 0; p < 8; p++) h += part[sl][p][lane];
            h1s[sl][lane] = fmaxf(h, 0.f);
        }
        __syncwarp();
        float h2 = __ldg(b2 + lane);
#pragma unroll
        for (int k = 0; k < 15; k++)
            h2 = fmaf(h1s[sl][k], __ldg(w2 + lane * 15 + k), h2);
        h2 = fmaxf(h2, 0.f);
        float ov = h2 * __ldg(w3 + lane);
#pragma unroll
        for (int s = 16; s; s >>= 1) ov += __shfl_xor_sync(0xffffffffu, ov, s);
        if (lane == 0) out[sample] = ov + __ldg(b3);
    }
}

// ---------------------------------------------------------------------------
extern "C" void kernel_launch(void* const* d_in, const int* in_sizes, int n_in,
                              void* d_out, int out_size) {
    const float *images = 0, *conv_w = 0, *ft_w = 0, *ft_b = 0;
    const float *w1 = 0, *b1 = 0, *w2 = 0, *b2 = 0, *w3 = 0, *b3 = 0;

    for (int i = 0; i < n_in; i++) {
        const float* p = (const float*)d_in[i];
        switch (in_sizes[i]) {
            case 28311552: images = p; break;
            case 216:      conv_w = p; break;
            case 819200:   ft_w   = p; break;
            case 1024:     ft_b   = p; break;
            case 15360:    w1     = p; break;
            case 15:       b1     = p; break;
            case 480:      w2     = p; break;
            case 32:       if (!b2) b2 = p; else w3 = p; break;
            case 1:        b3     = p; break;
            default: break;
        }
    }
    float* out = (float*)d_out;

    dummy_kernel<<<1, 32>>>();       // keeps ncu capture slot on feat_mma

    dim3 gt(L1D / 32, NF / 32);      // 32 x 25
    prep_bt_kernel<<<gt, 256>>>(ft_w);
    conv_act_kernel<<<B_SZ, 256>>>(images, conv_w);

    dim3 g2(L1D / 64, B_SZ / 64, 2); // 16 x 16 x 2 = 512 CTAs
    feat_mma_kernel<<<g2, 256>>>();

    tail_kernel<<<B_SZ / 2, 512>>>(ft_b, w1, b1, w2, b2, w3, b3, out);
}